// round 14
// baseline (speedup 1.0000x reference)
#include <cuda_runtime.h>
#include <cuda_bf16.h>
#include <cstdint>
#include <cstddef>

// Problem constants
#define BB 2
#define SS 2048
#define DD 1024
#define HH 16
#define DEP 64
#define BH (BB*HH)          // 32
#define NQB (SS/64)         // 32 key blocks of 64
#define NQT (SS/128)        // 16 query tiles of 128

// Scratch
__device__ float g_Qp[(size_t)BH * SS * DEP];
__device__ float g_Kp[(size_t)BH * SS * DEP];
__device__ float g_Vp[(size_t)BH * SS * DEP];
__device__ float g_Vbs[(size_t)BH * (NQB + 1) * DEP];
__device__ float g_Vpart[(size_t)BH * NQB * DEP];

#define TRUNC_HI(x) __uint_as_float(__float_as_uint(x) & 0xFFFFE000u)
#define TF32_BITS(x) (__float_as_uint(x) & 0xFFFFE000u)
__device__ __forceinline__ uint32_t rnd_tf32_bits(float x) {
    return (__float_as_uint(x) + 0x1000u) & 0xFFFFE000u;
}

__device__ __forceinline__ void split2(float x, uint32_t& h, uint32_t& l) {
    float hh = TRUNC_HI(x);
    h = __float_as_uint(hh);
    l = __float_as_uint(x - hh);
}

// m16n8k8 tf32 mma (arch-portable PTX; HMMA on sm_103)
__device__ __forceinline__ void mma_tf32(float* c, const uint32_t* a, const uint32_t* b) {
    asm volatile(
        "mma.sync.aligned.m16n8k8.row.col.f32.tf32.tf32.f32 "
        "{%0,%1,%2,%3}, {%4,%5,%6,%7}, {%8,%9}, {%0,%1,%2,%3};"
        : "+f"(c[0]), "+f"(c[1]), "+f"(c[2]), "+f"(c[3])
        : "r"(a[0]), "r"(a[1]), "r"(a[2]), "r"(a[3]), "r"(b[0]), "r"(b[1]));
}

__device__ __forceinline__ uint32_t smem_u32(const void* p) {
    uint32_t a;
    asm("{ .reg .u64 t; cvta.to.shared.u64 t, %1; cvt.u32.u64 %0, t; }"
        : "=r"(a) : "l"(p));
    return a;
}
__device__ __forceinline__ void cp16(uint32_t dst, const void* src) {
    asm volatile("cp.async.cg.shared.global [%0], [%1], 16;" :: "r"(dst), "l"(src));
}
#define CP_COMMIT() asm volatile("cp.async.commit_group;" ::: "memory")
#define CP_WAIT0()  asm volatile("cp.async.wait_group 0;" ::: "memory")
#define CP_WAIT1()  asm volatile("cp.async.wait_group 1;" ::: "memory")

// ---------------------------------------------------------------------------
// Kernel 1: split-tf32 projection GEMM, 3-stage cp.async pipeline.
// B staged raw from W [k][n] (BSTR=136, conflict-free). Q/K: 3 MMAs.
// V: 2 MMAs with rounded A. Q output pre-scaled by 0.125 (exact, pow2).
// ---------------------------------------------------------------------------
#define PSTR 36
#define BSTR 136
#define ABUF (128 * PSTR)                 // 4608 floats
#define PBUF (ABUF + 32 * BSTR)           // + 4352 = 8960 floats
#define PROJ_SMEM (3 * PBUF * 4)          // 107,520 B -> 2 CTAs/SM

__global__ __launch_bounds__(256, 2)
void proj_mma_kernel(const float* __restrict__ q, const float* __restrict__ k,
                     const float* __restrict__ v, const float* __restrict__ wq,
                     const float* __restrict__ wk, const float* __restrict__ wv) {
    extern __shared__ float sm[];
    const uint32_t sb = smem_u32(sm);

    const float* X;
    const float* W;
    float* Out;
    if (blockIdx.z == 0)      { X = q; W = wq; Out = g_Qp; }
    else if (blockIdx.z == 1) { X = k; W = wk; Out = g_Kp; }
    else                      { X = v; W = wv; Out = g_Vp; }
    const bool vsl = (blockIdx.z == 2);
    const float oscale = (blockIdx.z == 0) ? 0.125f : 1.0f;

    const int row0 = blockIdx.y * 128;
    const int n0   = blockIdx.x * 128;
    const int tid  = threadIdx.x;
    const int lane = tid & 31;
    const int wid  = tid >> 5;
    const int warpM = wid >> 1;
    const int warpN = wid & 1;
    const int g  = lane >> 2;
    const int tg = lane & 3;

    const float* Ag0 = X + (size_t)row0 * DD;
    const float* Wg0 = W + n0;

    float acc[2][8][4];
#pragma unroll
    for (int mt = 0; mt < 2; ++mt)
#pragma unroll
        for (int nt = 0; nt < 8; ++nt)
#pragma unroll
            for (int i = 0; i < 4; ++i) acc[mt][nt][i] = 0.f;

    int srow[4], skq[4];
#pragma unroll
    for (int j = 0; j < 4; ++j) {
        const int i = tid + (j << 8);
        srow[j] = i >> 3;
        skq[j]  = (i & 7) << 2;
    }
    const int bkk = tid >> 3;            // 0..31 (B k-row)
    const int bj  = (tid & 7) << 2;      // 0..28 (B n offset)

    auto stage_async = [&](int c, int bb) {
        const float* Ag = Ag0 + c * 32;
        const uint32_t base = sb + (uint32_t)bb * PBUF * 4;
#pragma unroll
        for (int j = 0; j < 4; ++j) {
            const uint32_t off = (uint32_t)(srow[j] * PSTR + skq[j]) * 4;
            cp16(base + off, Ag + (size_t)srow[j] * DD + skq[j]);
        }
        const size_t wrow = (size_t)(c * 32 + bkk) * DD;
#pragma unroll
        for (int j = 0; j < 4; ++j) {
            const int nn = bj + j * 32;
            cp16(base + (uint32_t)(ABUF + bkk * BSTR + nn) * 4, Wg0 + wrow + nn);
        }
        CP_COMMIT();
    };

    // 3-stage prologue: buffers 0 and 1 in flight; wait for 0 only.
    stage_async(0, 0);
    stage_async(1, 1);
    CP_WAIT1();
    __syncthreads();

    for (int c = 0; c < 32; ++c) {
        const int b = c % 3;
        if (c + 2 < 32) stage_async(c + 2, (c + 2) % 3);

        const float* As = sm + b * PBUF;
        const float* Bs = As + ABUF;

#pragma unroll
        for (int ks = 0; ks < 4; ++ks) {
            const int kof = ks * 8 + tg;
            uint32_t ah[2][4], al[2][4];
#pragma unroll
            for (int mt = 0; mt < 2; ++mt) {
                const int rr = (warpM * 32 + mt * 16 + g) * PSTR + kof;
                if (vsl) {
                    ah[mt][0] = rnd_tf32_bits(As[rr]);
                    ah[mt][1] = rnd_tf32_bits(As[rr + 8 * PSTR]);
                    ah[mt][2] = rnd_tf32_bits(As[rr + 4]);
                    ah[mt][3] = rnd_tf32_bits(As[rr + 8 * PSTR + 4]);
                } else {
                    split2(As[rr],                ah[mt][0], al[mt][0]);
                    split2(As[rr + 8 * PSTR],     ah[mt][1], al[mt][1]);
                    split2(As[rr + 4],            ah[mt][2], al[mt][2]);
                    split2(As[rr + 8 * PSTR + 4], ah[mt][3], al[mt][3]);
                }
            }
            const int brow0 = kof * BSTR;
            const int brow1 = (kof + 4) * BSTR;
#pragma unroll
            for (int nt = 0; nt < 8; ++nt) {
                const int n = warpN * 64 + nt * 8 + g;
                uint32_t bh[2], bl[2];
                split2(Bs[brow0 + n], bh[0], bl[0]);
                split2(Bs[brow1 + n], bh[1], bl[1]);
#pragma unroll
                for (int mt = 0; mt < 2; ++mt) {
                    mma_tf32(acc[mt][nt], ah[mt], bh);
                    mma_tf32(acc[mt][nt], ah[mt], bl);
                    if (!vsl) mma_tf32(acc[mt][nt], al[mt], bh);
                }
            }
        }

        if (c + 2 < 32)      CP_WAIT1();   // require stage(c+1) done; c+2 stays in flight
        else if (c + 1 < 32) CP_WAIT0();   // last copy: full drain
        __syncthreads();
    }

#pragma unroll
    for (int mt = 0; mt < 2; ++mt) {
        const int r0 = row0 + warpM * 32 + mt * 16 + g;
        const int r1 = r0 + 8;
        const int b0i = r0 >> 11, s0 = r0 & 2047;
        const int b1i = r1 >> 11, s1 = r1 & 2047;
#pragma unroll
        for (int nt = 0; nt < 8; ++nt) {
            const int n = n0 + warpN * 64 + nt * 8 + 2 * tg;
            const int h = n >> 6, dd = n & 63;
            float2 v01 = make_float2(acc[mt][nt][0] * oscale, acc[mt][nt][1] * oscale);
            float2 v23 = make_float2(acc[mt][nt][2] * oscale, acc[mt][nt][3] * oscale);
            *(float2*)(Out + (((size_t)b0i * HH + h) * SS + s0) * DEP + dd) = v01;
            *(float2*)(Out + (((size_t)b1i * HH + h) * SS + s1) * DEP + dd) = v23;
        }
    }
}

// ---------------------------------------------------------------------------
// Kernel 2a: round V to tf32 in place + per-block partial sums (of rounded V).
// Kernel 2b: suffix scan.
// ---------------------------------------------------------------------------
__global__ void vsuffix_part() {
    const int kb = blockIdx.x, bh = blockIdx.y;
    const int d  = threadIdx.x;
    float* vp = g_Vp + ((size_t)bh * SS + kb * 64) * DEP + d;
    float acc = 0.f;
#pragma unroll
    for (int s = 0; s < 64; ++s) {
        float x = __uint_as_float(rnd_tf32_bits(vp[s * DEP]));
        vp[s * DEP] = x;
        acc += x;
    }
    g_Vpart[((size_t)bh * NQB + kb) * DEP + d] = acc;
}

__global__ void vsuffix_scan() {
    const int bh = blockIdx.x;
    const int d  = threadIdx.x;
    float p[NQB];
#pragma unroll
    for (int kb = 0; kb < NQB; ++kb)
        p[kb] = g_Vpart[((size_t)bh * NQB + kb) * DEP + d];
    float acc = 0.f;
    g_Vbs[((size_t)bh * (NQB + 1) + NQB) * DEP + d] = 0.f;
#pragma unroll
    for (int kb = NQB - 1; kb >= 0; --kb) {
        acc += p[kb];
        g_Vbs[((size_t)bh * (NQB + 1) + kb) * DEP + d] = acc;
    }
}

// ---------------------------------------------------------------------------
// Kernel 3: tensor-core flash attention (R12 structure; Q pre-scaled, so no
// per-element score scaling here).
// ---------------------------------------------------------------------------
#define ASTR 68
#define ATTN_SMEM ((128*ASTR + 4*64*ASTR) * 4)   // 104,448 B

__global__ __launch_bounds__(256, 2)
void attn_mma_kernel(float* __restrict__ out) {
    extern __shared__ float sm[];
    const uint32_t sb = smem_u32(sm);
    float* Qs = sm;                      // [128][ASTR] raw (pre-scaled by 1/8)

    const int tid  = threadIdx.x;
    const int lane = tid & 31, w = tid >> 5;
    const int g = lane >> 2, tg = lane & 3;
    const int qt = NQT - 1 - blockIdx.x;     // longest-first
    const int bh = blockIdx.y;
    const int q0 = qt << 7;
    const int row0 = w * 16 + g;
    const int upper = (w < 4);
    const int diag_kb = 2 * qt + (upper ? 0 : 1);
    const int nkb = 2 * qt + 2;
    const int rl0 = row0 & 63;

    const float* Kg0 = g_Kp + (size_t)bh * SS * DEP;
    const float* Vg0 = g_Vp + (size_t)bh * SS * DEP;

    auto stage_kv = [&](int kb, int bb) {
        const float* Kg = Kg0 + ((size_t)kb << 6) * DEP;
        const float* Vg = Vg0 + ((size_t)kb << 6) * DEP;
        const uint32_t kbase = sb + (uint32_t)(128 + 128 * bb) * ASTR * 4;
        const uint32_t vbase = kbase + 64 * ASTR * 4;
#pragma unroll
        for (int i = 0; i < 4; ++i) {
            const int idx = tid + (i << 8);
            const int r = idx >> 4, c4 = (idx & 15) << 2;
            const uint32_t off = (uint32_t)(r * ASTR + c4) * 4;
            cp16(kbase + off, Kg + (size_t)r * DEP + c4);
            cp16(vbase + off, Vg + (size_t)r * DEP + c4);
        }
        CP_COMMIT();
    };

    {
        const float* Qg = g_Qp + ((size_t)bh * SS + q0) * DEP;
#pragma unroll
        for (int i = 0; i < 8; ++i) {
            const int idx = tid + (i << 8);
            const int r = idx >> 4, c4 = (idx & 15) << 2;
            cp16(sb + (uint32_t)(r * ASTR + c4) * 4, Qg + (size_t)r * DEP + c4);
        }
        CP_COMMIT();
        stage_kv(0, 0);
        CP_WAIT0();
        __syncthreads();
    }

    float m0 = -3.0e38f, m1 = -3.0e38f, l0 = 0.f, l1 = 0.f;
    float o[8][4];
#pragma unroll
    for (int nt = 0; nt < 8; ++nt)
#pragma unroll
        for (int i = 0; i < 4; ++i) o[nt][i] = 0.f;

    for (int kb = 0; kb < nkb; ++kb) {
        const int b = kb & 1;
        if (kb + 1 < nkb) stage_kv(kb + 1, 1 - b);

        const float* Ks = sm + (128 + 128 * b) * ASTR;
        const float* Vs = Ks + 64 * ASTR;

        const bool skip = upper && (kb == nkb - 1);
        if (!skip) {
            float s[8][4];
#pragma unroll
            for (int nt = 0; nt < 8; ++nt)
#pragma unroll
                for (int i = 0; i < 4; ++i) s[nt][i] = 0.f;

#pragma unroll
            for (int ks = 0; ks < 8; ++ks) {
                const int kof = ks * 8 + tg;
                const int rr = row0 * ASTR + kof;
                uint32_t ah[4], al[4];
                split2(Qs[rr],                ah[0], al[0]);
                split2(Qs[rr + 8 * ASTR],     ah[1], al[1]);
                split2(Qs[rr + 4],            ah[2], al[2]);
                split2(Qs[rr + 8 * ASTR + 4], ah[3], al[3]);
#pragma unroll
                for (int nt = 0; nt < 8; ++nt) {
                    const int cc = (nt * 8 + g) * ASTR + kof;
                    uint32_t kh[2], kl[2];
                    split2(Ks[cc],     kh[0], kl[0]);
                    split2(Ks[cc + 4], kh[1], kl[1]);
                    mma_tf32(s[nt], ah, kh);
                    mma_tf32(s[nt], ah, kl);
                    mma_tf32(s[nt], al, kh);
                }
            }

            // diagonal causal mask (-8.0 fill); scores already scaled via Q
            const bool diag = (kb == diag_kb);
            if (diag) {
#pragma unroll
                for (int nt = 0; nt < 8; ++nt) {
                    const int c0 = nt * 8 + 2 * tg;
#pragma unroll
                    for (int i = 0; i < 4; ++i) {
                        const int col  = c0 + (i & 1);
                        const int rowi = rl0 + ((i >> 1) << 3);
                        if (col > rowi) s[nt][i] = -8.0f;
                    }
                }
            }

            float pm0 = -3.0e38f, pm1 = -3.0e38f;
#pragma unroll
            for (int nt = 0; nt < 8; ++nt) {
                pm0 = fmaxf(pm0, fmaxf(s[nt][0], s[nt][1]));
                pm1 = fmaxf(pm1, fmaxf(s[nt][2], s[nt][3]));
            }
            pm0 = fmaxf(pm0, __shfl_xor_sync(0xffffffffu, pm0, 1));
            pm0 = fmaxf(pm0, __shfl_xor_sync(0xffffffffu, pm0, 2));
            pm1 = fmaxf(pm1, __shfl_xor_sync(0xffffffffu, pm1, 1));
            pm1 = fmaxf(pm1, __shfl_xor_sync(0xffffffffu, pm1, 2));
            const float mn0 = fmaxf(m0, pm0), mn1 = fmaxf(m1, pm1);
            const float rs0 = __expf(m0 - mn0), rs1 = __expf(m1 - mn1);

            float ps0 = 0.f, ps1 = 0.f;
#pragma unroll
            for (int nt = 0; nt < 8; ++nt) {
                float p0 = __expf(s[nt][0] - mn0);
                float p1 = __expf(s[nt][1] - mn0);
                float p2 = __expf(s[nt][2] - mn1);
                float p3 = __expf(s[nt][3] - mn1);
                ps0 += p0 + p1; ps1 += p2 + p3;
                s[nt][0] = p0; s[nt][1] = p1; s[nt][2] = p2; s[nt][3] = p3;
            }
            ps0 += __shfl_xor_sync(0xffffffffu, ps0, 1);
            ps0 += __shfl_xor_sync(0xffffffffu, ps0, 2);
            ps1 += __shfl_xor_sync(0xffffffffu, ps1, 1);
            ps1 += __shfl_xor_sync(0xffffffffu, ps1, 2);
            l0 = l0 * rs0 + ps0;
            l1 = l1 * rs1 + ps1;
            m0 = mn0; m1 = mn1;

#pragma unroll
            for (int nt = 0; nt < 8; ++nt) {
                o[nt][0] *= rs0; o[nt][1] *= rs0;
                o[nt][2] *= rs1; o[nt][3] *= rs1;
            }

            const int src0 = 4 * g + (tg >> 1);
            const int src1 = src0 + 2;
            const bool oddt = (tg & 1);
#pragma unroll
            for (int ks = 0; ks < 8; ++ks) {
                float q00 = __shfl_sync(0xffffffffu, s[ks][0], src0);
                float q01 = __shfl_sync(0xffffffffu, s[ks][1], src0);
                float q02 = __shfl_sync(0xffffffffu, s[ks][2], src0);
                float q03 = __shfl_sync(0xffffffffu, s[ks][3], src0);
                float q10 = __shfl_sync(0xffffffffu, s[ks][0], src1);
                float q11 = __shfl_sync(0xffffffffu, s[ks][1], src1);
                float q12 = __shfl_sync(0xffffffffu, s[ks][2], src1);
                float q13 = __shfl_sync(0xffffffffu, s[ks][3], src1);
                uint32_t ph[4];
                ph[0] = TF32_BITS(oddt ? q01 : q00);
                ph[1] = TF32_BITS(oddt ? q03 : q02);
                ph[2] = TF32_BITS(oddt ? q11 : q10);
                ph[3] = TF32_BITS(oddt ? q13 : q12);
#pragma unroll
                for (int nt = 0; nt < 8; ++nt) {
                    const int vc = (ks * 8 + tg) * ASTR + nt * 8 + g;
                    uint32_t vh[2];
                    vh[0] = __float_as_uint(Vs[vc]);
                    vh[1] = __float_as_uint(Vs[vc + 4 * ASTR]);
                    mma_tf32(o[nt], ph, vh);
                }
            }
        }

        if (kb + 1 < nkb) CP_WAIT0();
        __syncthreads();
    }

    const int tailblk = nkb - (upper ? 1 : 0);
    const int cnt = SS - tailblk * 64;
    if (cnt > 0) {
        const float mn0 = fmaxf(m0, -8.0f), mn1 = fmaxf(m1, -8.0f);
        const float rs0 = __expf(m0 - mn0), rs1 = __expf(m1 - mn1);
        const float p0 = __expf(-8.0f - mn0), p1 = __expf(-8.0f - mn1);
        l0 = l0 * rs0 + (float)cnt * p0;
        l1 = l1 * rs1 + (float)cnt * p1;
        const float* vb = g_Vbs + ((size_t)bh * (NQB + 1) + tailblk) * DEP;
#pragma unroll
        for (int nt = 0; nt < 8; ++nt) {
            const int c = nt * 8 + 2 * tg;
            float2 vv = *(const float2*)(vb + c);
            o[nt][0] = o[nt][0] * rs0 + p0 * vv.x;
            o[nt][1] = o[nt][1] * rs0 + p0 * vv.y;
            o[nt][2] = o[nt][2] * rs1 + p1 * vv.x;
            o[nt][3] = o[nt][3] * rs1 + p1 * vv.y;
        }
    }

    const float inv0 = 1.f / l0, inv1 = 1.f / l1;
    const int b = bh >> 4, h = bh & 15;
    float* op0 = out + ((size_t)b * SS + q0 + row0) * DD + h * DEP;
    float* op1 = op0 + (size_t)8 * DD;
#pragma unroll
    for (int nt = 0; nt < 8; ++nt) {
        const int c = nt * 8 + 2 * tg;
        *(float2*)(op0 + c) = make_float2(o[nt][0] * inv0, o[nt][1] * inv0);
        *(float2*)(op1 + c) = make_float2(o[nt][2] * inv1, o[nt][3] * inv1);
    }
}

// ---------------------------------------------------------------------------
extern "C" void kernel_launch(void* const* d_in, const int* in_sizes, int n_in,
                              void* d_out, int out_size) {
    const float* q  = (const float*)d_in[0];
    const float* k  = (const float*)d_in[1];
    const float* v  = (const float*)d_in[2];
    // d_in[3] is the causal mask (tril) — handled analytically.
    const float* wq = (const float*)d_in[4];
    const float* wk = (const float*)d_in[5];
    const float* wv = (const float*)d_in[6];
    float* out = (float*)d_out;

    cudaFuncSetAttribute(proj_mma_kernel, cudaFuncAttributeMaxDynamicSharedMemorySize,
                         PROJ_SMEM);
    cudaFuncSetAttribute(attn_mma_kernel, cudaFuncAttributeMaxDynamicSharedMemorySize,
                         ATTN_SMEM);

    proj_mma_kernel<<<dim3(8, 32, 3), 256, PROJ_SMEM>>>(q, k, v, wq, wk, wv);
    vsuffix_part<<<dim3(NQB, BH), DEP>>>();
    vsuffix_scan<<<BH, DEP>>>();
    attn_mma_kernel<<<dim3(NQT, BH), 256, ATTN_SMEM>>>(out);
}

// round 15
// speedup vs baseline: 1.0141x; 1.0141x over previous
#include <cuda_runtime.h>
#include <cuda_bf16.h>
#include <cstdint>
#include <cstddef>

// Problem constants
#define BB 2
#define SS 2048
#define DD 1024
#define HH 16
#define DEP 64
#define BH (BB*HH)          // 32
#define NQB (SS/64)         // 32 key blocks of 64
#define NQT (SS/128)        // 16 query tiles of 128

// Scratch
__device__ float g_Qp[(size_t)BH * SS * DEP];
__device__ float g_Kp[(size_t)BH * SS * DEP];
__device__ float g_Vp[(size_t)BH * SS * DEP];
__device__ float g_Vbs[(size_t)BH * (NQB + 1) * DEP];
__device__ float g_Vpart[(size_t)BH * NQB * DEP];

#define TRUNC_HI(x) __uint_as_float(__float_as_uint(x) & 0xFFFFE000u)
#define TF32_BITS(x) (__float_as_uint(x) & 0xFFFFE000u)
__device__ __forceinline__ uint32_t rnd_tf32_bits(float x) {
    return (__float_as_uint(x) + 0x1000u) & 0xFFFFE000u;
}

__device__ __forceinline__ void split2(float x, uint32_t& h, uint32_t& l) {
    float hh = TRUNC_HI(x);
    h = __float_as_uint(hh);
    l = __float_as_uint(x - hh);
}

// m16n8k8 tf32 mma (arch-portable PTX; HMMA on sm_103)
__device__ __forceinline__ void mma_tf32(float* c, const uint32_t* a, const uint32_t* b) {
    asm volatile(
        "mma.sync.aligned.m16n8k8.row.col.f32.tf32.tf32.f32 "
        "{%0,%1,%2,%3}, {%4,%5,%6,%7}, {%8,%9}, {%0,%1,%2,%3};"
        : "+f"(c[0]), "+f"(c[1]), "+f"(c[2]), "+f"(c[3])
        : "r"(a[0]), "r"(a[1]), "r"(a[2]), "r"(a[3]), "r"(b[0]), "r"(b[1]));
}

__device__ __forceinline__ uint32_t smem_u32(const void* p) {
    uint32_t a;
    asm("{ .reg .u64 t; cvta.to.shared.u64 t, %1; cvt.u32.u64 %0, t; }"
        : "=r"(a) : "l"(p));
    return a;
}
__device__ __forceinline__ void cp16(uint32_t dst, const void* src) {
    asm volatile("cp.async.cg.shared.global [%0], [%1], 16;" :: "r"(dst), "l"(src));
}
#define CP_COMMIT() asm volatile("cp.async.commit_group;" ::: "memory")
#define CP_WAIT0()  asm volatile("cp.async.wait_group 0;" ::: "memory")

// ---------------------------------------------------------------------------
// Kernel 1: split-tf32 projection GEMM, cp.async double-buffered (R12).
// B staged raw from W [k][n] (BSTR=136, conflict-free). Q/K: 3 MMAs.
// V: 2 MMAs with rounded A. Q output pre-scaled by 0.125 (exact, pow2).
// ---------------------------------------------------------------------------
#define PSTR 36
#define BSTR 136
#define ABUF (128 * PSTR)                 // 4608 floats
#define PBUF (ABUF + 32 * BSTR)           // + 4352 = 8960 floats
#define PROJ_SMEM (2 * PBUF * 4)          // 71,680 B -> 2 CTAs/SM

__global__ __launch_bounds__(256, 2)
void proj_mma_kernel(const float* __restrict__ q, const float* __restrict__ k,
                     const float* __restrict__ v, const float* __restrict__ wq,
                     const float* __restrict__ wk, const float* __restrict__ wv) {
    extern __shared__ float sm[];
    const uint32_t sb = smem_u32(sm);

    const float* X;
    const float* W;
    float* Out;
    if (blockIdx.z == 0)      { X = q; W = wq; Out = g_Qp; }
    else if (blockIdx.z == 1) { X = k; W = wk; Out = g_Kp; }
    else                      { X = v; W = wv; Out = g_Vp; }
    const bool vsl = (blockIdx.z == 2);
    const float oscale = (blockIdx.z == 0) ? 0.125f : 1.0f;

    const int row0 = blockIdx.y * 128;
    const int n0   = blockIdx.x * 128;
    const int tid  = threadIdx.x;
    const int lane = tid & 31;
    const int wid  = tid >> 5;
    const int warpM = wid >> 1;
    const int warpN = wid & 1;
    const int g  = lane >> 2;
    const int tg = lane & 3;

    const float* Ag0 = X + (size_t)row0 * DD;
    const float* Wg0 = W + n0;

    float acc[2][8][4];
#pragma unroll
    for (int mt = 0; mt < 2; ++mt)
#pragma unroll
        for (int nt = 0; nt < 8; ++nt)
#pragma unroll
            for (int i = 0; i < 4; ++i) acc[mt][nt][i] = 0.f;

    int srow[4], skq[4];
#pragma unroll
    for (int j = 0; j < 4; ++j) {
        const int i = tid + (j << 8);
        srow[j] = i >> 3;
        skq[j]  = (i & 7) << 2;
    }
    const int bkk = tid >> 3;            // 0..31 (B k-row)
    const int bj  = (tid & 7) << 2;      // 0..28 (B n offset)

    auto stage_async = [&](int c, int bb) {
        const float* Ag = Ag0 + c * 32;
        const uint32_t base = sb + (uint32_t)bb * PBUF * 4;
#pragma unroll
        for (int j = 0; j < 4; ++j) {
            const uint32_t off = (uint32_t)(srow[j] * PSTR + skq[j]) * 4;
            cp16(base + off, Ag + (size_t)srow[j] * DD + skq[j]);
        }
        const size_t wrow = (size_t)(c * 32 + bkk) * DD;
#pragma unroll
        for (int j = 0; j < 4; ++j) {
            const int nn = bj + j * 32;
            cp16(base + (uint32_t)(ABUF + bkk * BSTR + nn) * 4, Wg0 + wrow + nn);
        }
        CP_COMMIT();
    };

    stage_async(0, 0);
    CP_WAIT0();
    __syncthreads();

    for (int c = 0; c < 32; ++c) {
        const int b = c & 1;
        if (c < 31) stage_async(c + 1, 1 - b);

        const float* As = sm + b * PBUF;
        const float* Bs = As + ABUF;

#pragma unroll
        for (int ks = 0; ks < 4; ++ks) {
            const int kof = ks * 8 + tg;
            uint32_t ah[2][4], al[2][4];
#pragma unroll
            for (int mt = 0; mt < 2; ++mt) {
                const int rr = (warpM * 32 + mt * 16 + g) * PSTR + kof;
                if (vsl) {
                    ah[mt][0] = rnd_tf32_bits(As[rr]);
                    ah[mt][1] = rnd_tf32_bits(As[rr + 8 * PSTR]);
                    ah[mt][2] = rnd_tf32_bits(As[rr + 4]);
                    ah[mt][3] = rnd_tf32_bits(As[rr + 8 * PSTR + 4]);
                } else {
                    split2(As[rr],                ah[mt][0], al[mt][0]);
                    split2(As[rr + 8 * PSTR],     ah[mt][1], al[mt][1]);
                    split2(As[rr + 4],            ah[mt][2], al[mt][2]);
                    split2(As[rr + 8 * PSTR + 4], ah[mt][3], al[mt][3]);
                }
            }
            const int brow0 = kof * BSTR;
            const int brow1 = (kof + 4) * BSTR;
#pragma unroll
            for (int nt = 0; nt < 8; ++nt) {
                const int n = warpN * 64 + nt * 8 + g;
                uint32_t bh[2], bl[2];
                split2(Bs[brow0 + n], bh[0], bl[0]);
                split2(Bs[brow1 + n], bh[1], bl[1]);
#pragma unroll
                for (int mt = 0; mt < 2; ++mt) {
                    mma_tf32(acc[mt][nt], ah[mt], bh);
                    mma_tf32(acc[mt][nt], ah[mt], bl);
                    if (!vsl) mma_tf32(acc[mt][nt], al[mt], bh);
                }
            }
        }

        if (c < 31) CP_WAIT0();
        __syncthreads();
    }

#pragma unroll
    for (int mt = 0; mt < 2; ++mt) {
        const int r0 = row0 + warpM * 32 + mt * 16 + g;
        const int r1 = r0 + 8;
        const int b0i = r0 >> 11, s0 = r0 & 2047;
        const int b1i = r1 >> 11, s1 = r1 & 2047;
#pragma unroll
        for (int nt = 0; nt < 8; ++nt) {
            const int n = n0 + warpN * 64 + nt * 8 + 2 * tg;
            const int h = n >> 6, dd = n & 63;
            float2 v01 = make_float2(acc[mt][nt][0] * oscale, acc[mt][nt][1] * oscale);
            float2 v23 = make_float2(acc[mt][nt][2] * oscale, acc[mt][nt][3] * oscale);
            *(float2*)(Out + (((size_t)b0i * HH + h) * SS + s0) * DEP + dd) = v01;
            *(float2*)(Out + (((size_t)b1i * HH + h) * SS + s1) * DEP + dd) = v23;
        }
    }
}

// ---------------------------------------------------------------------------
// Kernel 2a: round V to tf32 in place + per-block partial sums (of rounded V).
// Kernel 2b: suffix scan.
// ---------------------------------------------------------------------------
__global__ void vsuffix_part() {
    const int kb = blockIdx.x, bh = blockIdx.y;
    const int d  = threadIdx.x;
    float* vp = g_Vp + ((size_t)bh * SS + kb * 64) * DEP + d;
    float acc = 0.f;
#pragma unroll
    for (int s = 0; s < 64; ++s) {
        float x = __uint_as_float(rnd_tf32_bits(vp[s * DEP]));
        vp[s * DEP] = x;
        acc += x;
    }
    g_Vpart[((size_t)bh * NQB + kb) * DEP + d] = acc;
}

__global__ void vsuffix_scan() {
    const int bh = blockIdx.x;
    const int d  = threadIdx.x;
    float p[NQB];
#pragma unroll
    for (int kb = 0; kb < NQB; ++kb)
        p[kb] = g_Vpart[((size_t)bh * NQB + kb) * DEP + d];
    float acc = 0.f;
    g_Vbs[((size_t)bh * (NQB + 1) + NQB) * DEP + d] = 0.f;
#pragma unroll
    for (int kb = NQB - 1; kb >= 0; --kb) {
        acc += p[kb];
        g_Vbs[((size_t)bh * (NQB + 1) + kb) * DEP + d] = acc;
    }
}

// ---------------------------------------------------------------------------
// Kernel 3: tensor-core flash attention (R12 structure; Q pre-scaled,
// mask applied only on diagonal tiles).
// ---------------------------------------------------------------------------
#define ASTR 68
#define ATTN_SMEM ((128*ASTR + 4*64*ASTR) * 4)   // 104,448 B

__global__ __launch_bounds__(256, 2)
void attn_mma_kernel(float* __restrict__ out) {
    extern __shared__ float sm[];
    const uint32_t sb = smem_u32(sm);
    float* Qs = sm;                      // [128][ASTR] raw (pre-scaled by 1/8)

    const int tid  = threadIdx.x;
    const int lane = tid & 31, w = tid >> 5;
    const int g = lane >> 2, tg = lane & 3;
    const int qt = NQT - 1 - blockIdx.x;     // longest-first
    const int bh = blockIdx.y;
    const int q0 = qt << 7;
    const int row0 = w * 16 + g;
    const int upper = (w < 4);
    const int diag_kb = 2 * qt + (upper ? 0 : 1);
    const int nkb = 2 * qt + 2;
    const int rl0 = row0 & 63;

    const float* Kg0 = g_Kp + (size_t)bh * SS * DEP;
    const float* Vg0 = g_Vp + (size_t)bh * SS * DEP;

    auto stage_kv = [&](int kb, int bb) {
        const float* Kg = Kg0 + ((size_t)kb << 6) * DEP;
        const float* Vg = Vg0 + ((size_t)kb << 6) * DEP;
        const uint32_t kbase = sb + (uint32_t)(128 + 128 * bb) * ASTR * 4;
        const uint32_t vbase = kbase + 64 * ASTR * 4;
#pragma unroll
        for (int i = 0; i < 4; ++i) {
            const int idx = tid + (i << 8);
            const int r = idx >> 4, c4 = (idx & 15) << 2;
            const uint32_t off = (uint32_t)(r * ASTR + c4) * 4;
            cp16(kbase + off, Kg + (size_t)r * DEP + c4);
            cp16(vbase + off, Vg + (size_t)r * DEP + c4);
        }
        CP_COMMIT();
    };

    {
        const float* Qg = g_Qp + ((size_t)bh * SS + q0) * DEP;
#pragma unroll
        for (int i = 0; i < 8; ++i) {
            const int idx = tid + (i << 8);
            const int r = idx >> 4, c4 = (idx & 15) << 2;
            cp16(sb + (uint32_t)(r * ASTR + c4) * 4, Qg + (size_t)r * DEP + c4);
        }
        CP_COMMIT();
        stage_kv(0, 0);
        CP_WAIT0();
        __syncthreads();
    }

    float m0 = -3.0e38f, m1 = -3.0e38f, l0 = 0.f, l1 = 0.f;
    float o[8][4];
#pragma unroll
    for (int nt = 0; nt < 8; ++nt)
#pragma unroll
        for (int i = 0; i < 4; ++i) o[nt][i] = 0.f;

    for (int kb = 0; kb < nkb; ++kb) {
        const int b = kb & 1;
        if (kb + 1 < nkb) stage_kv(kb + 1, 1 - b);

        const float* Ks = sm + (128 + 128 * b) * ASTR;
        const float* Vs = Ks + 64 * ASTR;

        const bool skip = upper && (kb == nkb - 1);
        if (!skip) {
            float s[8][4];
#pragma unroll
            for (int nt = 0; nt < 8; ++nt)
#pragma unroll
                for (int i = 0; i < 4; ++i) s[nt][i] = 0.f;

#pragma unroll
            for (int ks = 0; ks < 8; ++ks) {
                const int kof = ks * 8 + tg;
                const int rr = row0 * ASTR + kof;
                uint32_t ah[4], al[4];
                split2(Qs[rr],                ah[0], al[0]);
                split2(Qs[rr + 8 * ASTR],     ah[1], al[1]);
                split2(Qs[rr + 4],            ah[2], al[2]);
                split2(Qs[rr + 8 * ASTR + 4], ah[3], al[3]);
#pragma unroll
                for (int nt = 0; nt < 8; ++nt) {
                    const int cc = (nt * 8 + g) * ASTR + kof;
                    uint32_t kh[2], kl[2];
                    split2(Ks[cc],     kh[0], kl[0]);
                    split2(Ks[cc + 4], kh[1], kl[1]);
                    mma_tf32(s[nt], ah, kh);
                    mma_tf32(s[nt], ah, kl);
                    mma_tf32(s[nt], al, kh);
                }
            }

            // diagonal causal mask (-8.0 fill); scores pre-scaled via Q
            if (kb == diag_kb) {
#pragma unroll
                for (int nt = 0; nt < 8; ++nt) {
                    const int c0 = nt * 8 + 2 * tg;
#pragma unroll
                    for (int i = 0; i < 4; ++i) {
                        const int col  = c0 + (i & 1);
                        const int rowi = rl0 + ((i >> 1) << 3);
                        if (col > rowi) s[nt][i] = -8.0f;
                    }
                }
            }

            float pm0 = -3.0e38f, pm1 = -3.0e38f;
#pragma unroll
            for (int nt = 0; nt < 8; ++nt) {
                pm0 = fmaxf(pm0, fmaxf(s[nt][0], s[nt][1]));
                pm1 = fmaxf(pm1, fmaxf(s[nt][2], s[nt][3]));
            }
            pm0 = fmaxf(pm0, __shfl_xor_sync(0xffffffffu, pm0, 1));
            pm0 = fmaxf(pm0, __shfl_xor_sync(0xffffffffu, pm0, 2));
            pm1 = fmaxf(pm1, __shfl_xor_sync(0xffffffffu, pm1, 1));
            pm1 = fmaxf(pm1, __shfl_xor_sync(0xffffffffu, pm1, 2));
            const float mn0 = fmaxf(m0, pm0), mn1 = fmaxf(m1, pm1);
            const float rs0 = __expf(m0 - mn0), rs1 = __expf(m1 - mn1);

            float ps0 = 0.f, ps1 = 0.f;
#pragma unroll
            for (int nt = 0; nt < 8; ++nt) {
                float p0 = __expf(s[nt][0] - mn0);
                float p1 = __expf(s[nt][1] - mn0);
                float p2 = __expf(s[nt][2] - mn1);
                float p3 = __expf(s[nt][3] - mn1);
                ps0 += p0 + p1; ps1 += p2 + p3;
                s[nt][0] = p0; s[nt][1] = p1; s[nt][2] = p2; s[nt][3] = p3;
            }
            ps0 += __shfl_xor_sync(0xffffffffu, ps0, 1);
            ps0 += __shfl_xor_sync(0xffffffffu, ps0, 2);
            ps1 += __shfl_xor_sync(0xffffffffu, ps1, 1);
            ps1 += __shfl_xor_sync(0xffffffffu, ps1, 2);
            l0 = l0 * rs0 + ps0;
            l1 = l1 * rs1 + ps1;
            m0 = mn0; m1 = mn1;

#pragma unroll
            for (int nt = 0; nt < 8; ++nt) {
                o[nt][0] *= rs0; o[nt][1] *= rs0;
                o[nt][2] *= rs1; o[nt][3] *= rs1;
            }

            const int src0 = 4 * g + (tg >> 1);
            const int src1 = src0 + 2;
            const bool oddt = (tg & 1);
#pragma unroll
            for (int ks = 0; ks < 8; ++ks) {
                float q00 = __shfl_sync(0xffffffffu, s[ks][0], src0);
                float q01 = __shfl_sync(0xffffffffu, s[ks][1], src0);
                float q02 = __shfl_sync(0xffffffffu, s[ks][2], src0);
                float q03 = __shfl_sync(0xffffffffu, s[ks][3], src0);
                float q10 = __shfl_sync(0xffffffffu, s[ks][0], src1);
                float q11 = __shfl_sync(0xffffffffu, s[ks][1], src1);
                float q12 = __shfl_sync(0xffffffffu, s[ks][2], src1);
                float q13 = __shfl_sync(0xffffffffu, s[ks][3], src1);
                uint32_t ph[4];
                ph[0] = TF32_BITS(oddt ? q01 : q00);
                ph[1] = TF32_BITS(oddt ? q03 : q02);
                ph[2] = TF32_BITS(oddt ? q11 : q10);
                ph[3] = TF32_BITS(oddt ? q13 : q12);
#pragma unroll
                for (int nt = 0; nt < 8; ++nt) {
                    const int vc = (ks * 8 + tg) * ASTR + nt * 8 + g;
                    uint32_t vh[2];
                    vh[0] = __float_as_uint(Vs[vc]);
                    vh[1] = __float_as_uint(Vs[vc + 4 * ASTR]);
                    mma_tf32(o[nt], ph, vh);
                }
            }
        }

        if (kb + 1 < nkb) CP_WAIT0();
        __syncthreads();
    }

    const int tailblk = nkb - (upper ? 1 : 0);
    const int cnt = SS - tailblk * 64;
    if (cnt > 0) {
        const float mn0 = fmaxf(m0, -8.0f), mn1 = fmaxf(m1, -8.0f);
        const float rs0 = __expf(m0 - mn0), rs1 = __expf(m1 - mn1);
        const float p0 = __expf(-8.0f - mn0), p1 = __expf(-8.0f - mn1);
        l0 = l0 * rs0 + (float)cnt * p0;
        l1 = l1 * rs1 + (float)cnt * p1;
        const float* vb = g_Vbs + ((size_t)bh * (NQB + 1) + tailblk) * DEP;
#pragma unroll
        for (int nt = 0; nt < 8; ++nt) {
            const int c = nt * 8 + 2 * tg;
            float2 vv = *(const float2*)(vb + c);
            o[nt][0] = o[nt][0] * rs0 + p0 * vv.x;
            o[nt][1] = o[nt][1] * rs0 + p0 * vv.y;
            o[nt][2] = o[nt][2] * rs1 + p1 * vv.x;
            o[nt][3] = o[nt][3] * rs1 + p1 * vv.y;
        }
    }

    const float inv0 = 1.f / l0, inv1 = 1.f / l1;
    const int b = bh >> 4, h = bh & 15;
    float* op0 = out + ((size_t)b * SS + q0 + row0) * DD + h * DEP;
    float* op1 = op0 + (size_t)8 * DD;
#pragma unroll
    for (int nt = 0; nt < 8; ++nt) {
        const int c = nt * 8 + 2 * tg;
        *(float2*)(op0 + c) = make_float2(o[nt][0] * inv0, o[nt][1] * inv0);
        *(float2*)(op1 + c) = make_float2(o[nt][2] * inv1, o[nt][3] * inv1);
    }
}

// ---------------------------------------------------------------------------
extern "C" void kernel_launch(void* const* d_in, const int* in_sizes, int n_in,
                              void* d_out, int out_size) {
    const float* q  = (const float*)d_in[0];
    const float* k  = (const float*)d_in[1];
    const float* v  = (const float*)d_in[2];
    // d_in[3] is the causal mask (tril) — handled analytically.
    const float* wq = (const float*)d_in[4];
    const float* wk = (const float*)d_in[5];
    const float* wv = (const float*)d_in[6];
    float* out = (float*)d_out;

    cudaFuncSetAttribute(proj_mma_kernel, cudaFuncAttributeMaxDynamicSharedMemorySize,
                         PROJ_SMEM);
    cudaFuncSetAttribute(attn_mma_kernel, cudaFuncAttributeMaxDynamicSharedMemorySize,
                         ATTN_SMEM);

    proj_mma_kernel<<<dim3(8, 32, 3), 256, PROJ_SMEM>>>(q, k, v, wq, wk, wv);
    vsuffix_part<<<dim3(NQB, BH), DEP>>>();
    vsuffix_scan<<<BH, DEP>>>();
    attn_mma_kernel<<<dim3(NQT, BH), 256, ATTN_SMEM>>>(out);
}

// round 16
// speedup vs baseline: 1.5763x; 1.5544x over previous
#include <cuda_runtime.h>
#include <cuda_bf16.h>
#include <cstdint>
#include <cstddef>

// Problem constants
#define BB 2
#define SS 2048
#define DD 1024
#define HH 16
#define DEP 64
#define BH (BB*HH)          // 32
#define NQB (SS/64)         // 32 key blocks of 64
#define NQT (SS/128)        // 16 query tiles of 128

// Scratch
__device__ float g_Qp[(size_t)BH * SS * DEP];
__device__ float g_Kp[(size_t)BH * SS * DEP];
__device__ float g_Vp[(size_t)BH * SS * DEP];
__device__ float g_Vbs[(size_t)BH * (NQB + 1) * DEP];
__device__ float g_Vpart[(size_t)BH * NQB * DEP];

#define TRUNC_HI(x) __uint_as_float(__float_as_uint(x) & 0xFFFFE000u)
#define TF32_BITS(x) (__float_as_uint(x) & 0xFFFFE000u)
__device__ __forceinline__ uint32_t rnd_tf32_bits(float x) {
    return (__float_as_uint(x) + 0x1000u) & 0xFFFFE000u;
}

__device__ __forceinline__ void split2(float x, uint32_t& h, uint32_t& l) {
    float hh = TRUNC_HI(x);
    h = __float_as_uint(hh);
    l = __float_as_uint(x - hh);
}

// m16n8k8 tf32 mma (arch-portable PTX; HMMA on sm_103)
__device__ __forceinline__ void mma_tf32(float* c, const uint32_t* a, const uint32_t* b) {
    asm volatile(
        "mma.sync.aligned.m16n8k8.row.col.f32.tf32.tf32.f32 "
        "{%0,%1,%2,%3}, {%4,%5,%6,%7}, {%8,%9}, {%0,%1,%2,%3};"
        : "+f"(c[0]), "+f"(c[1]), "+f"(c[2]), "+f"(c[3])
        : "r"(a[0]), "r"(a[1]), "r"(a[2]), "r"(a[3]), "r"(b[0]), "r"(b[1]));
}

__device__ __forceinline__ uint32_t smem_u32(const void* p) {
    uint32_t a;
    asm("{ .reg .u64 t; cvta.to.shared.u64 t, %1; cvt.u32.u64 %0, t; }"
        : "=r"(a) : "l"(p));
    return a;
}
__device__ __forceinline__ void cp16(uint32_t dst, const void* src) {
    asm volatile("cp.async.cg.shared.global [%0], [%1], 16;" :: "r"(dst), "l"(src));
}
#define CP_COMMIT() asm volatile("cp.async.commit_group;" ::: "memory")
#define CP_WAIT0()  asm volatile("cp.async.wait_group 0;" ::: "memory")

// ---------------------------------------------------------------------------
// Kernel 1: split-tf32 projection GEMM, cp.async double-buffered (R12).
// B staged raw from W [k][n] (BSTR=136, conflict-free). Q/K: 3 MMAs.
// V: 2 MMAs with rounded A. Q output pre-scaled by 0.125 (exact, pow2).
// V output rounded to tf32 at store (moves the rounding out of vsuffix).
// ---------------------------------------------------------------------------
#define PSTR 36
#define BSTR 136
#define ABUF (128 * PSTR)                 // 4608 floats
#define PBUF (ABUF + 32 * BSTR)           // + 4352 = 8960 floats
#define PROJ_SMEM (2 * PBUF * 4)          // 71,680 B -> 2 CTAs/SM

__global__ __launch_bounds__(256, 2)
void proj_mma_kernel(const float* __restrict__ q, const float* __restrict__ k,
                     const float* __restrict__ v, const float* __restrict__ wq,
                     const float* __restrict__ wk, const float* __restrict__ wv) {
    extern __shared__ float sm[];
    const uint32_t sb = smem_u32(sm);

    const float* X;
    const float* W;
    float* Out;
    if (blockIdx.z == 0)      { X = q; W = wq; Out = g_Qp; }
    else if (blockIdx.z == 1) { X = k; W = wk; Out = g_Kp; }
    else                      { X = v; W = wv; Out = g_Vp; }
    const bool vsl = (blockIdx.z == 2);
    const float oscale = (blockIdx.z == 0) ? 0.125f : 1.0f;

    const int row0 = blockIdx.y * 128;
    const int n0   = blockIdx.x * 128;
    const int tid  = threadIdx.x;
    const int lane = tid & 31;
    const int wid  = tid >> 5;
    const int warpM = wid >> 1;
    const int warpN = wid & 1;
    const int g  = lane >> 2;
    const int tg = lane & 3;

    const float* Ag0 = X + (size_t)row0 * DD;
    const float* Wg0 = W + n0;

    float acc[2][8][4];
#pragma unroll
    for (int mt = 0; mt < 2; ++mt)
#pragma unroll
        for (int nt = 0; nt < 8; ++nt)
#pragma unroll
            for (int i = 0; i < 4; ++i) acc[mt][nt][i] = 0.f;

    int srow[4], skq[4];
#pragma unroll
    for (int j = 0; j < 4; ++j) {
        const int i = tid + (j << 8);
        srow[j] = i >> 3;
        skq[j]  = (i & 7) << 2;
    }
    const int bkk = tid >> 3;            // 0..31 (B k-row)
    const int bj  = (tid & 7) << 2;      // 0..28 (B n offset)

    auto stage_async = [&](int c, int bb) {
        const float* Ag = Ag0 + c * 32;
        const uint32_t base = sb + (uint32_t)bb * PBUF * 4;
#pragma unroll
        for (int j = 0; j < 4; ++j) {
            const uint32_t off = (uint32_t)(srow[j] * PSTR + skq[j]) * 4;
            cp16(base + off, Ag + (size_t)srow[j] * DD + skq[j]);
        }
        const size_t wrow = (size_t)(c * 32 + bkk) * DD;
#pragma unroll
        for (int j = 0; j < 4; ++j) {
            const int nn = bj + j * 32;
            cp16(base + (uint32_t)(ABUF + bkk * BSTR + nn) * 4, Wg0 + wrow + nn);
        }
        CP_COMMIT();
    };

    stage_async(0, 0);
    CP_WAIT0();
    __syncthreads();

    for (int c = 0; c < 32; ++c) {
        const int b = c & 1;
        if (c < 31) stage_async(c + 1, 1 - b);

        const float* As = sm + b * PBUF;
        const float* Bs = As + ABUF;

#pragma unroll
        for (int ks = 0; ks < 4; ++ks) {
            const int kof = ks * 8 + tg;
            uint32_t ah[2][4], al[2][4];
#pragma unroll
            for (int mt = 0; mt < 2; ++mt) {
                const int rr = (warpM * 32 + mt * 16 + g) * PSTR + kof;
                if (vsl) {
                    ah[mt][0] = rnd_tf32_bits(As[rr]);
                    ah[mt][1] = rnd_tf32_bits(As[rr + 8 * PSTR]);
                    ah[mt][2] = rnd_tf32_bits(As[rr + 4]);
                    ah[mt][3] = rnd_tf32_bits(As[rr + 8 * PSTR + 4]);
                } else {
                    split2(As[rr],                ah[mt][0], al[mt][0]);
                    split2(As[rr + 8 * PSTR],     ah[mt][1], al[mt][1]);
                    split2(As[rr + 4],            ah[mt][2], al[mt][2]);
                    split2(As[rr + 8 * PSTR + 4], ah[mt][3], al[mt][3]);
                }
            }
            const int brow0 = kof * BSTR;
            const int brow1 = (kof + 4) * BSTR;
#pragma unroll
            for (int nt = 0; nt < 8; ++nt) {
                const int n = warpN * 64 + nt * 8 + g;
                uint32_t bh[2], bl[2];
                split2(Bs[brow0 + n], bh[0], bl[0]);
                split2(Bs[brow1 + n], bh[1], bl[1]);
#pragma unroll
                for (int mt = 0; mt < 2; ++mt) {
                    mma_tf32(acc[mt][nt], ah[mt], bh);
                    mma_tf32(acc[mt][nt], ah[mt], bl);
                    if (!vsl) mma_tf32(acc[mt][nt], al[mt], bh);
                }
            }
        }

        if (c < 31) CP_WAIT0();
        __syncthreads();
    }

#pragma unroll
    for (int mt = 0; mt < 2; ++mt) {
        const int r0 = row0 + warpM * 32 + mt * 16 + g;
        const int r1 = r0 + 8;
        const int b0i = r0 >> 11, s0 = r0 & 2047;
        const int b1i = r1 >> 11, s1 = r1 & 2047;
#pragma unroll
        for (int nt = 0; nt < 8; ++nt) {
            const int n = n0 + warpN * 64 + nt * 8 + 2 * tg;
            const int h = n >> 6, dd = n & 63;
            float2 v01, v23;
            if (vsl) {   // V: round to tf32 at store (consumed rounded everywhere)
                v01.x = __uint_as_float(rnd_tf32_bits(acc[mt][nt][0]));
                v01.y = __uint_as_float(rnd_tf32_bits(acc[mt][nt][1]));
                v23.x = __uint_as_float(rnd_tf32_bits(acc[mt][nt][2]));
                v23.y = __uint_as_float(rnd_tf32_bits(acc[mt][nt][3]));
            } else {
                v01 = make_float2(acc[mt][nt][0] * oscale, acc[mt][nt][1] * oscale);
                v23 = make_float2(acc[mt][nt][2] * oscale, acc[mt][nt][3] * oscale);
            }
            *(float2*)(Out + (((size_t)b0i * HH + h) * SS + s0) * DEP + dd) = v01;
            *(float2*)(Out + (((size_t)b1i * HH + h) * SS + s1) * DEP + dd) = v23;
        }
    }
}

// ---------------------------------------------------------------------------
// Kernel 2a: per-block partial sums of (already-rounded) V — read-only.
// Kernel 2b: suffix scan.
// ---------------------------------------------------------------------------
__global__ void vsuffix_part() {
    const int kb = blockIdx.x, bh = blockIdx.y;
    const int d  = threadIdx.x;
    const float* vp = g_Vp + ((size_t)bh * SS + kb * 64) * DEP + d;
    float acc = 0.f;
#pragma unroll
    for (int s = 0; s < 64; ++s) acc += vp[s * DEP];
    g_Vpart[((size_t)bh * NQB + kb) * DEP + d] = acc;
}

__global__ void vsuffix_scan() {
    const int bh = blockIdx.x;
    const int d  = threadIdx.x;
    float p[NQB];
#pragma unroll
    for (int kb = 0; kb < NQB; ++kb)
        p[kb] = g_Vpart[((size_t)bh * NQB + kb) * DEP + d];
    float acc = 0.f;
    g_Vbs[((size_t)bh * (NQB + 1) + NQB) * DEP + d] = 0.f;
#pragma unroll
    for (int kb = NQB - 1; kb >= 0; --kb) {
        acc += p[kb];
        g_Vbs[((size_t)bh * (NQB + 1) + kb) * DEP + d] = acc;
    }
}

// ---------------------------------------------------------------------------
// Kernel 3: tensor-core flash attention (Q pre-scaled, V pre-rounded in gmem,
// mask applied only on diagonal tiles).
// ---------------------------------------------------------------------------
#define ASTR 68
#define ATTN_SMEM ((128*ASTR + 4*64*ASTR) * 4)   // 104,448 B

__global__ __launch_bounds__(256, 2)
void attn_mma_kernel(float* __restrict__ out) {
    extern __shared__ float sm[];
    const uint32_t sb = smem_u32(sm);
    float* Qs = sm;                      // [128][ASTR] raw (pre-scaled by 1/8)

    const int tid  = threadIdx.x;
    const int lane = tid & 31, w = tid >> 5;
    const int g = lane >> 2, tg = lane & 3;
    const int qt = NQT - 1 - blockIdx.x;     // longest-first
    const int bh = blockIdx.y;
    const int q0 = qt << 7;
    const int row0 = w * 16 + g;
    const int upper = (w < 4);
    const int diag_kb = 2 * qt + (upper ? 0 : 1);
    const int nkb = 2 * qt + 2;
    const int rl0 = row0 & 63;

    const float* Kg0 = g_Kp + (size_t)bh * SS * DEP;
    const float* Vg0 = g_Vp + (size_t)bh * SS * DEP;

    auto stage_kv = [&](int kb, int bb) {
        const float* Kg = Kg0 + ((size_t)kb << 6) * DEP;
        const float* Vg = Vg0 + ((size_t)kb << 6) * DEP;
        const uint32_t kbase = sb + (uint32_t)(128 + 128 * bb) * ASTR * 4;
        const uint32_t vbase = kbase + 64 * ASTR * 4;
#pragma unroll
        for (int i = 0; i < 4; ++i) {
            const int idx = tid + (i << 8);
            const int r = idx >> 4, c4 = (idx & 15) << 2;
            const uint32_t off = (uint32_t)(r * ASTR + c4) * 4;
            cp16(kbase + off, Kg + (size_t)r * DEP + c4);
            cp16(vbase + off, Vg + (size_t)r * DEP + c4);
        }
        CP_COMMIT();
    };

    {
        const float* Qg = g_Qp + ((size_t)bh * SS + q0) * DEP;
#pragma unroll
        for (int i = 0; i < 8; ++i) {
            const int idx = tid + (i << 8);
            const int r = idx >> 4, c4 = (idx & 15) << 2;
            cp16(sb + (uint32_t)(r * ASTR + c4) * 4, Qg + (size_t)r * DEP + c4);
        }
        CP_COMMIT();
        stage_kv(0, 0);
        CP_WAIT0();
        __syncthreads();
    }

    float m0 = -3.0e38f, m1 = -3.0e38f, l0 = 0.f, l1 = 0.f;
    float o[8][4];
#pragma unroll
    for (int nt = 0; nt < 8; ++nt)
#pragma unroll
        for (int i = 0; i < 4; ++i) o[nt][i] = 0.f;

    for (int kb = 0; kb < nkb; ++kb) {
        const int b = kb & 1;
        if (kb + 1 < nkb) stage_kv(kb + 1, 1 - b);

        const float* Ks = sm + (128 + 128 * b) * ASTR;
        const float* Vs = Ks + 64 * ASTR;

        const bool skip = upper && (kb == nkb - 1);
        if (!skip) {
            float s[8][4];
#pragma unroll
            for (int nt = 0; nt < 8; ++nt)
#pragma unroll
                for (int i = 0; i < 4; ++i) s[nt][i] = 0.f;

#pragma unroll
            for (int ks = 0; ks < 8; ++ks) {
                const int kof = ks * 8 + tg;
                const int rr = row0 * ASTR + kof;
                uint32_t ah[4], al[4];
                split2(Qs[rr],                ah[0], al[0]);
                split2(Qs[rr + 8 * ASTR],     ah[1], al[1]);
                split2(Qs[rr + 4],            ah[2], al[2]);
                split2(Qs[rr + 8 * ASTR + 4], ah[3], al[3]);
#pragma unroll
                for (int nt = 0; nt < 8; ++nt) {
                    const int cc = (nt * 8 + g) * ASTR + kof;
                    uint32_t kh[2], kl[2];
                    split2(Ks[cc],     kh[0], kl[0]);
                    split2(Ks[cc + 4], kh[1], kl[1]);
                    mma_tf32(s[nt], ah, kh);
                    mma_tf32(s[nt], ah, kl);
                    mma_tf32(s[nt], al, kh);
                }
            }

            if (kb == diag_kb) {
#pragma unroll
                for (int nt = 0; nt < 8; ++nt) {
                    const int c0 = nt * 8 + 2 * tg;
#pragma unroll
                    for (int i = 0; i < 4; ++i) {
                        const int col  = c0 + (i & 1);
                        const int rowi = rl0 + ((i >> 1) << 3);
                        if (col > rowi) s[nt][i] = -8.0f;
                    }
                }
            }

            float pm0 = -3.0e38f, pm1 = -3.0e38f;
#pragma unroll
            for (int nt = 0; nt < 8; ++nt) {
                pm0 = fmaxf(pm0, fmaxf(s[nt][0], s[nt][1]));
                pm1 = fmaxf(pm1, fmaxf(s[nt][2], s[nt][3]));
            }
            pm0 = fmaxf(pm0, __shfl_xor_sync(0xffffffffu, pm0, 1));
            pm0 = fmaxf(pm0, __shfl_xor_sync(0xffffffffu, pm0, 2));
            pm1 = fmaxf(pm1, __shfl_xor_sync(0xffffffffu, pm1, 1));
            pm1 = fmaxf(pm1, __shfl_xor_sync(0xffffffffu, pm1, 2));
            const float mn0 = fmaxf(m0, pm0), mn1 = fmaxf(m1, pm1);
            const float rs0 = __expf(m0 - mn0), rs1 = __expf(m1 - mn1);

            float ps0 = 0.f, ps1 = 0.f;
#pragma unroll
            for (int nt = 0; nt < 8; ++nt) {
                float p0 = __expf(s[nt][0] - mn0);
                float p1 = __expf(s[nt][1] - mn0);
                float p2 = __expf(s[nt][2] - mn1);
                float p3 = __expf(s[nt][3] - mn1);
                ps0 += p0 + p1; ps1 += p2 + p3;
                s[nt][0] = p0; s[nt][1] = p1; s[nt][2] = p2; s[nt][3] = p3;
            }
            ps0 += __shfl_xor_sync(0xffffffffu, ps0, 1);
            ps0 += __shfl_xor_sync(0xffffffffu, ps0, 2);
            ps1 += __shfl_xor_sync(0xffffffffu, ps1, 1);
            ps1 += __shfl_xor_sync(0xffffffffu, ps1, 2);
            l0 = l0 * rs0 + ps0;
            l1 = l1 * rs1 + ps1;
            m0 = mn0; m1 = mn1;

#pragma unroll
            for (int nt = 0; nt < 8; ++nt) {
                o[nt][0] *= rs0; o[nt][1] *= rs0;
                o[nt][2] *= rs1; o[nt][3] *= rs1;
            }

            const int src0 = 4 * g + (tg >> 1);
            const int src1 = src0 + 2;
            const bool oddt = (tg & 1);
#pragma unroll
            for (int ks = 0; ks < 8; ++ks) {
                float q00 = __shfl_sync(0xffffffffu, s[ks][0], src0);
                float q01 = __shfl_sync(0xffffffffu, s[ks][1], src0);
                float q02 = __shfl_sync(0xffffffffu, s[ks][2], src0);
                float q03 = __shfl_sync(0xffffffffu, s[ks][3], src0);
                float q10 = __shfl_sync(0xffffffffu, s[ks][0], src1);
                float q11 = __shfl_sync(0xffffffffu, s[ks][1], src1);
                float q12 = __shfl_sync(0xffffffffu, s[ks][2], src1);
                float q13 = __shfl_sync(0xffffffffu, s[ks][3], src1);
                uint32_t ph[4];
                ph[0] = TF32_BITS(oddt ? q01 : q00);
                ph[1] = TF32_BITS(oddt ? q03 : q02);
                ph[2] = TF32_BITS(oddt ? q11 : q10);
                ph[3] = TF32_BITS(oddt ? q13 : q12);
#pragma unroll
                for (int nt = 0; nt < 8; ++nt) {
                    const int vc = (ks * 8 + tg) * ASTR + nt * 8 + g;
                    uint32_t vh[2];
                    vh[0] = __float_as_uint(Vs[vc]);
                    vh[1] = __float_as_uint(Vs[vc + 4 * ASTR]);
                    mma_tf32(o[nt], ph, vh);
                }
            }
        }

        if (kb + 1 < nkb) CP_WAIT0();
        __syncthreads();
    }

    const int tailblk = nkb - (upper ? 1 : 0);
    const int cnt = SS - tailblk * 64;
    if (cnt > 0) {
        const float mn0 = fmaxf(m0, -8.0f), mn1 = fmaxf(m1, -8.0f);
        const float rs0 = __expf(m0 - mn0), rs1 = __expf(m1 - mn1);
        const float p0 = __expf(-8.0f - mn0), p1 = __expf(-8.0f - mn1);
        l0 = l0 * rs0 + (float)cnt * p0;
        l1 = l1 * rs1 + (float)cnt * p1;
        const float* vb = g_Vbs + ((size_t)bh * (NQB + 1) + tailblk) * DEP;
#pragma unroll
        for (int nt = 0; nt < 8; ++nt) {
            const int c = nt * 8 + 2 * tg;
            float2 vv = *(const float2*)(vb + c);
            o[nt][0] = o[nt][0] * rs0 + p0 * vv.x;
            o[nt][1] = o[nt][1] * rs0 + p0 * vv.y;
            o[nt][2] = o[nt][2] * rs1 + p1 * vv.x;
            o[nt][3] = o[nt][3] * rs1 + p1 * vv.y;
        }
    }

    const float inv0 = 1.f / l0, inv1 = 1.f / l1;
    const int b = bh >> 4, h = bh & 15;
    float* op0 = out + ((size_t)b * SS + q0 + row0) * DD + h * DEP;
    float* op1 = op0 + (size_t)8 * DD;
#pragma unroll
    for (int nt = 0; nt < 8; ++nt) {
        const int c = nt * 8 + 2 * tg;
        *(float2*)(op0 + c) = make_float2(o[nt][0] * inv0, o[nt][1] * inv0);
        *(float2*)(op1 + c) = make_float2(o[nt][2] * inv1, o[nt][3] * inv1);
    }
}

// ---------------------------------------------------------------------------
extern "C" void kernel_launch(void* const* d_in, const int* in_sizes, int n_in,
                              void* d_out, int out_size) {
    const float* q  = (const float*)d_in[0];
    const float* k  = (const float*)d_in[1];
    const float* v  = (const float*)d_in[2];
    // d_in[3] is the causal mask (tril) — handled analytically.
    const float* wq = (const float*)d_in[4];
    const float* wk = (const float*)d_in[5];
    const float* wv = (const float*)d_in[6];
    float* out = (float*)d_out;

    cudaFuncSetAttribute(proj_mma_kernel, cudaFuncAttributeMaxDynamicSharedMemorySize,
                         PROJ_SMEM);
    cudaFuncSetAttribute(attn_mma_kernel, cudaFuncAttributeMaxDynamicSharedMemorySize,
                         ATTN_SMEM);

    proj_mma_kernel<<<dim3(8, 32, 3), 256, PROJ_SMEM>>>(q, k, v, wq, wk, wv);
    vsuffix_part<<<dim3(NQB, BH), DEP>>>();
    vsuffix_scan<<<BH, DEP>>>();
    attn_mma_kernel<<<dim3(NQT, BH), 256, ATTN_SMEM>>>(out);
}

// round 17
// speedup vs baseline: 1.6366x; 1.0382x over previous
#include <cuda_runtime.h>
#include <cuda_bf16.h>
#include <cstdint>
#include <cstddef>

// Problem constants
#define BB 2
#define SS 2048
#define DD 1024
#define HH 16
#define DEP 64
#define BH (BB*HH)          // 32
#define NQB (SS/64)         // 32 key blocks of 64
#define NQT (SS/128)        // 16 query tiles of 128

// Scratch.  g_Qp/g_Kp hold the d-dimension PERMUTED within 8-wide groups:
// feature c stored at (c & ~7) | ((c&3)<<1) | ((c&4)>>2)   ({0,4,1,5,2,6,3,7}).
// QK^T is invariant; mask indexes keys (rows); V/output unpermuted.
__device__ float g_Qp[(size_t)BH * SS * DEP];
__device__ float g_Kp[(size_t)BH * SS * DEP];
__device__ float g_Vp[(size_t)BH * SS * DEP];
__device__ float g_Vbs[(size_t)BH * (NQB + 1) * DEP];
__device__ float g_Vpart[(size_t)BH * NQB * DEP];

#define TRUNC_HI(x) __uint_as_float(__float_as_uint(x) & 0xFFFFE000u)
#define TF32_BITS(x) (__float_as_uint(x) & 0xFFFFE000u)
#define DPERM(c) (((c) & ~7) | ((((c) & 3) << 1) | (((c) & 4) >> 2)))
__device__ __forceinline__ uint32_t rnd_tf32_bits(float x) {
    return (__float_as_uint(x) + 0x1000u) & 0xFFFFE000u;
}

__device__ __forceinline__ void split2(float x, uint32_t& h, uint32_t& l) {
    float hh = TRUNC_HI(x);
    h = __float_as_uint(hh);
    l = __float_as_uint(x - hh);
}

// m16n8k8 tf32 mma (arch-portable PTX; HMMA on sm_103)
__device__ __forceinline__ void mma_tf32(float* c, const uint32_t* a, const uint32_t* b) {
    asm volatile(
        "mma.sync.aligned.m16n8k8.row.col.f32.tf32.tf32.f32 "
        "{%0,%1,%2,%3}, {%4,%5,%6,%7}, {%8,%9}, {%0,%1,%2,%3};"
        : "+f"(c[0]), "+f"(c[1]), "+f"(c[2]), "+f"(c[3])
        : "r"(a[0]), "r"(a[1]), "r"(a[2]), "r"(a[3]), "r"(b[0]), "r"(b[1]));
}

__device__ __forceinline__ uint32_t smem_u32(const void* p) {
    uint32_t a;
    asm("{ .reg .u64 t; cvta.to.shared.u64 t, %1; cvt.u32.u64 %0, t; }"
        : "=r"(a) : "l"(p));
    return a;
}
__device__ __forceinline__ void cp16(uint32_t dst, const void* src) {
    asm volatile("cp.async.cg.shared.global [%0], [%1], 16;" :: "r"(dst), "l"(src));
}
#define CP_COMMIT() asm volatile("cp.async.commit_group;" ::: "memory")
#define CP_WAIT0()  asm volatile("cp.async.wait_group 0;" ::: "memory")

// ---------------------------------------------------------------------------
// Kernel 1: split-tf32 projection GEMM, cp.async double-buffered.
// Q/K outputs written with permuted d-dim (scalar stores); V rounded+float2.
// ---------------------------------------------------------------------------
#define PSTR 36
#define BSTR 136
#define ABUF (128 * PSTR)
#define PBUF (ABUF + 32 * BSTR)
#define PROJ_SMEM (2 * PBUF * 4)          // 71,680 B -> 2 CTAs/SM

__global__ __launch_bounds__(256, 2)
void proj_mma_kernel(const float* __restrict__ q, const float* __restrict__ k,
                     const float* __restrict__ v, const float* __restrict__ wq,
                     const float* __restrict__ wk, const float* __restrict__ wv) {
    extern __shared__ float sm[];
    const uint32_t sb = smem_u32(sm);

    const float* X;
    const float* W;
    float* Out;
    if (blockIdx.z == 0)      { X = q; W = wq; Out = g_Qp; }
    else if (blockIdx.z == 1) { X = k; W = wk; Out = g_Kp; }
    else                      { X = v; W = wv; Out = g_Vp; }
    const bool vsl = (blockIdx.z == 2);
    const float oscale = (blockIdx.z == 0) ? 0.125f : 1.0f;

    const int row0 = blockIdx.y * 128;
    const int n0   = blockIdx.x * 128;
    const int tid  = threadIdx.x;
    const int lane = tid & 31;
    const int wid  = tid >> 5;
    const int warpM = wid >> 1;
    const int warpN = wid & 1;
    const int g  = lane >> 2;
    const int tg = lane & 3;

    const float* Ag0 = X + (size_t)row0 * DD;
    const float* Wg0 = W + n0;

    float acc[2][8][4];
#pragma unroll
    for (int mt = 0; mt < 2; ++mt)
#pragma unroll
        for (int nt = 0; nt < 8; ++nt)
#pragma unroll
            for (int i = 0; i < 4; ++i) acc[mt][nt][i] = 0.f;

    int srow[4], skq[4];
#pragma unroll
    for (int j = 0; j < 4; ++j) {
        const int i = tid + (j << 8);
        srow[j] = i >> 3;
        skq[j]  = (i & 7) << 2;
    }
    const int bkk = tid >> 3;
    const int bj  = (tid & 7) << 2;

    auto stage_async = [&](int c, int bb) {
        const float* Ag = Ag0 + c * 32;
        const uint32_t base = sb + (uint32_t)bb * PBUF * 4;
#pragma unroll
        for (int j = 0; j < 4; ++j) {
            const uint32_t off = (uint32_t)(srow[j] * PSTR + skq[j]) * 4;
            cp16(base + off, Ag + (size_t)srow[j] * DD + skq[j]);
        }
        const size_t wrow = (size_t)(c * 32 + bkk) * DD;
#pragma unroll
        for (int j = 0; j < 4; ++j) {
            const int nn = bj + j * 32;
            cp16(base + (uint32_t)(ABUF + bkk * BSTR + nn) * 4, Wg0 + wrow + nn);
        }
        CP_COMMIT();
    };

    stage_async(0, 0);
    CP_WAIT0();
    __syncthreads();

    for (int c = 0; c < 32; ++c) {
        const int b = c & 1;
        if (c < 31) stage_async(c + 1, 1 - b);

        const float* As = sm + b * PBUF;
        const float* Bs = As + ABUF;

#pragma unroll
        for (int ks = 0; ks < 4; ++ks) {
            const int kof = ks * 8 + tg;
            uint32_t ah[2][4], al[2][4];
#pragma unroll
            for (int mt = 0; mt < 2; ++mt) {
                const int rr = (warpM * 32 + mt * 16 + g) * PSTR + kof;
                if (vsl) {
                    ah[mt][0] = rnd_tf32_bits(As[rr]);
                    ah[mt][1] = rnd_tf32_bits(As[rr + 8 * PSTR]);
                    ah[mt][2] = rnd_tf32_bits(As[rr + 4]);
                    ah[mt][3] = rnd_tf32_bits(As[rr + 8 * PSTR + 4]);
                } else {
                    split2(As[rr],                ah[mt][0], al[mt][0]);
                    split2(As[rr + 8 * PSTR],     ah[mt][1], al[mt][1]);
                    split2(As[rr + 4],            ah[mt][2], al[mt][2]);
                    split2(As[rr + 8 * PSTR + 4], ah[mt][3], al[mt][3]);
                }
            }
            const int brow0 = kof * BSTR;
            const int brow1 = (kof + 4) * BSTR;
#pragma unroll
            for (int nt = 0; nt < 8; ++nt) {
                const int n = warpN * 64 + nt * 8 + g;
                uint32_t bh[2], bl[2];
                split2(Bs[brow0 + n], bh[0], bl[0]);
                split2(Bs[brow1 + n], bh[1], bl[1]);
#pragma unroll
                for (int mt = 0; mt < 2; ++mt) {
                    mma_tf32(acc[mt][nt], ah[mt], bh);
                    mma_tf32(acc[mt][nt], ah[mt], bl);
                    if (!vsl) mma_tf32(acc[mt][nt], al[mt], bh);
                }
            }
        }

        if (c < 31) CP_WAIT0();
        __syncthreads();
    }

#pragma unroll
    for (int mt = 0; mt < 2; ++mt) {
        const int r0 = row0 + warpM * 32 + mt * 16 + g;
        const int r1 = r0 + 8;
        const int b0i = r0 >> 11, s0 = r0 & 2047;
        const int b1i = r1 >> 11, s1 = r1 & 2047;
#pragma unroll
        for (int nt = 0; nt < 8; ++nt) {
            const int n = n0 + warpN * 64 + nt * 8 + 2 * tg;
            const int h = n >> 6, dd = n & 63;
            float* o0 = Out + (((size_t)b0i * HH + h) * SS + s0) * DEP;
            float* o1 = Out + (((size_t)b1i * HH + h) * SS + s1) * DEP;
            if (vsl) {   // V: round to tf32 at store, unpermuted, vectorized
                float2 v01, v23;
                v01.x = __uint_as_float(rnd_tf32_bits(acc[mt][nt][0]));
                v01.y = __uint_as_float(rnd_tf32_bits(acc[mt][nt][1]));
                v23.x = __uint_as_float(rnd_tf32_bits(acc[mt][nt][2]));
                v23.y = __uint_as_float(rnd_tf32_bits(acc[mt][nt][3]));
                *(float2*)(o0 + dd) = v01;
                *(float2*)(o1 + dd) = v23;
            } else {     // Q/K: permuted d-dim scalar stores (Q pre-scaled)
                const int p0 = DPERM(dd);
                const int p1 = DPERM(dd + 1);
                o0[p0] = acc[mt][nt][0] * oscale;
                o0[p1] = acc[mt][nt][1] * oscale;
                o1[p0] = acc[mt][nt][2] * oscale;
                o1[p1] = acc[mt][nt][3] * oscale;
            }
        }
    }
}

// ---------------------------------------------------------------------------
// Kernel 2a: per-block partial sums of (already-rounded) V — read-only.
// Kernel 2b: suffix scan.
// ---------------------------------------------------------------------------
__global__ void vsuffix_part() {
    const int kb = blockIdx.x, bh = blockIdx.y;
    const int d  = threadIdx.x;
    const float* vp = g_Vp + ((size_t)bh * SS + kb * 64) * DEP + d;
    float acc = 0.f;
#pragma unroll
    for (int s = 0; s < 64; ++s) acc += vp[s * DEP];
    g_Vpart[((size_t)bh * NQB + kb) * DEP + d] = acc;
}

__global__ void vsuffix_scan() {
    const int bh = blockIdx.x;
    const int d  = threadIdx.x;
    float p[NQB];
#pragma unroll
    for (int kb = 0; kb < NQB; ++kb)
        p[kb] = g_Vpart[((size_t)bh * NQB + kb) * DEP + d];
    float acc = 0.f;
    g_Vbs[((size_t)bh * (NQB + 1) + NQB) * DEP + d] = 0.f;
#pragma unroll
    for (int kb = NQB - 1; kb >= 0; --kb) {
        acc += p[kb];
        g_Vbs[((size_t)bh * (NQB + 1) + kb) * DEP + d] = acc;
    }
}

// ---------------------------------------------------------------------------
// Kernel 3: tensor-core flash attention.
// Q/K feature-permuted in gmem -> QK fragment pairs load as single LDS.64.
// ASTR=72: permuted Q/K float2 loads AND V scalar loads all conflict-free.
// ---------------------------------------------------------------------------
#define ASTR 72
#define ATTN_SMEM ((128*ASTR + 4*64*ASTR) * 4)   // 110,592 B -> 2 CTAs/SM

__global__ __launch_bounds__(256, 2)
void attn_mma_kernel(float* __restrict__ out) {
    extern __shared__ float sm[];
    const uint32_t sb = smem_u32(sm);
    float* Qs = sm;                      // [128][ASTR] permuted-d, pre-scaled

    const int tid  = threadIdx.x;
    const int lane = tid & 31, w = tid >> 5;
    const int g = lane >> 2, tg = lane & 3;
    const int qt = NQT - 1 - blockIdx.x;     // longest-first
    const int bh = blockIdx.y;
    const int q0 = qt << 7;
    const int row0 = w * 16 + g;
    const int upper = (w < 4);
    const int diag_kb = 2 * qt + (upper ? 0 : 1);
    const int nkb = 2 * qt + 2;
    const int rl0 = row0 & 63;

    const float* Kg0 = g_Kp + (size_t)bh * SS * DEP;
    const float* Vg0 = g_Vp + (size_t)bh * SS * DEP;

    auto stage_kv = [&](int kb, int bb) {
        const float* Kg = Kg0 + ((size_t)kb << 6) * DEP;
        const float* Vg = Vg0 + ((size_t)kb << 6) * DEP;
        const uint32_t kbase = sb + (uint32_t)(128 + 128 * bb) * ASTR * 4;
        const uint32_t vbase = kbase + 64 * ASTR * 4;
#pragma unroll
        for (int i = 0; i < 4; ++i) {
            const int idx = tid + (i << 8);
            const int r = idx >> 4, c4 = (idx & 15) << 2;
            const uint32_t off = (uint32_t)(r * ASTR + c4) * 4;
            cp16(kbase + off, Kg + (size_t)r * DEP + c4);
            cp16(vbase + off, Vg + (size_t)r * DEP + c4);
        }
        CP_COMMIT();
    };

    {
        const float* Qg = g_Qp + ((size_t)bh * SS + q0) * DEP;
#pragma unroll
        for (int i = 0; i < 8; ++i) {
            const int idx = tid + (i << 8);
            const int r = idx >> 4, c4 = (idx & 15) << 2;
            cp16(sb + (uint32_t)(r * ASTR + c4) * 4, Qg + (size_t)r * DEP + c4);
        }
        CP_COMMIT();
        stage_kv(0, 0);
        CP_WAIT0();
        __syncthreads();
    }

    float m0 = -3.0e38f, m1 = -3.0e38f, l0 = 0.f, l1 = 0.f;
    float o[8][4];
#pragma unroll
    for (int nt = 0; nt < 8; ++nt)
#pragma unroll
        for (int i = 0; i < 4; ++i) o[nt][i] = 0.f;

    for (int kb = 0; kb < nkb; ++kb) {
        const int b = kb & 1;
        if (kb + 1 < nkb) stage_kv(kb + 1, 1 - b);

        const float* Ks = sm + (128 + 128 * b) * ASTR;
        const float* Vs = Ks + 64 * ASTR;

        const bool skip = upper && (kb == nkb - 1);
        if (!skip) {
            float s[8][4];
#pragma unroll
            for (int nt = 0; nt < 8; ++nt)
#pragma unroll
                for (int i = 0; i < 4; ++i) s[nt][i] = 0.f;

#pragma unroll
            for (int ks = 0; ks < 8; ++ks) {
                const int kof2 = ks * 8 + 2 * tg;       // permuted pair (kof, kof+4)
                const int rr = row0 * ASTR + kof2;
                float2 qa0 = *(const float2*)(Qs + rr);
                float2 qa1 = *(const float2*)(Qs + rr + 8 * ASTR);
                uint32_t ah[4], al[4];
                split2(qa0.x, ah[0], al[0]);
                split2(qa1.x, ah[1], al[1]);
                split2(qa0.y, ah[2], al[2]);
                split2(qa1.y, ah[3], al[3]);
#pragma unroll
                for (int nt = 0; nt < 8; ++nt) {
                    const int cc = (nt * 8 + g) * ASTR + kof2;
                    float2 kv = *(const float2*)(Ks + cc);
                    uint32_t kh[2], kl[2];
                    split2(kv.x, kh[0], kl[0]);
                    split2(kv.y, kh[1], kl[1]);
                    mma_tf32(s[nt], ah, kh);
                    mma_tf32(s[nt], ah, kl);
                    mma_tf32(s[nt], al, kh);
                }
            }

            if (kb == diag_kb) {
#pragma unroll
                for (int nt = 0; nt < 8; ++nt) {
                    const int c0 = nt * 8 + 2 * tg;
#pragma unroll
                    for (int i = 0; i < 4; ++i) {
                        const int col  = c0 + (i & 1);
                        const int rowi = rl0 + ((i >> 1) << 3);
                        if (col > rowi) s[nt][i] = -8.0f;
                    }
                }
            }

            float pm0 = -3.0e38f, pm1 = -3.0e38f;
#pragma unroll
            for (int nt = 0; nt < 8; ++nt) {
                pm0 = fmaxf(pm0, fmaxf(s[nt][0], s[nt][1]));
                pm1 = fmaxf(pm1, fmaxf(s[nt][2], s[nt][3]));
            }
            pm0 = fmaxf(pm0, __shfl_xor_sync(0xffffffffu, pm0, 1));
            pm0 = fmaxf(pm0, __shfl_xor_sync(0xffffffffu, pm0, 2));
            pm1 = fmaxf(pm1, __shfl_xor_sync(0xffffffffu, pm1, 1));
            pm1 = fmaxf(pm1, __shfl_xor_sync(0xffffffffu, pm1, 2));
            const float mn0 = fmaxf(m0, pm0), mn1 = fmaxf(m1, pm1);
            const float rs0 = __expf(m0 - mn0), rs1 = __expf(m1 - mn1);

            float ps0 = 0.f, ps1 = 0.f;
#pragma unroll
            for (int nt = 0; nt < 8; ++nt) {
                float p0 = __expf(s[nt][0] - mn0);
                float p1 = __expf(s[nt][1] - mn0);
                float p2 = __expf(s[nt][2] - mn1);
                float p3 = __expf(s[nt][3] - mn1);
                ps0 += p0 + p1; ps1 += p2 + p3;
                s[nt][0] = p0; s[nt][1] = p1; s[nt][2] = p2; s[nt][3] = p3;
            }
            ps0 += __shfl_xor_sync(0xffffffffu, ps0, 1);
            ps0 += __shfl_xor_sync(0xffffffffu, ps0, 2);
            ps1 += __shfl_xor_sync(0xffffffffu, ps1, 1);
            ps1 += __shfl_xor_sync(0xffffffffu, ps1, 2);
            l0 = l0 * rs0 + ps0;
            l1 = l1 * rs1 + ps1;
            m0 = mn0; m1 = mn1;

#pragma unroll
            for (int nt = 0; nt < 8; ++nt) {
                o[nt][0] *= rs0; o[nt][1] *= rs0;
                o[nt][2] *= rs1; o[nt][3] *= rs1;
            }

            const int src0 = 4 * g + (tg >> 1);
            const int src1 = src0 + 2;
            const bool oddt = (tg & 1);
#pragma unroll
            for (int ks = 0; ks < 8; ++ks) {
                float q00 = __shfl_sync(0xffffffffu, s[ks][0], src0);
                float q01 = __shfl_sync(0xffffffffu, s[ks][1], src0);
                float q02 = __shfl_sync(0xffffffffu, s[ks][2], src0);
                float q03 = __shfl_sync(0xffffffffu, s[ks][3], src0);
                float q10 = __shfl_sync(0xffffffffu, s[ks][0], src1);
                float q11 = __shfl_sync(0xffffffffu, s[ks][1], src1);
                float q12 = __shfl_sync(0xffffffffu, s[ks][2], src1);
                float q13 = __shfl_sync(0xffffffffu, s[ks][3], src1);
                uint32_t ph[4];
                ph[0] = TF32_BITS(oddt ? q01 : q00);
                ph[1] = TF32_BITS(oddt ? q03 : q02);
                ph[2] = TF32_BITS(oddt ? q11 : q10);
                ph[3] = TF32_BITS(oddt ? q13 : q12);
#pragma unroll
                for (int nt = 0; nt < 8; ++nt) {
                    const int vc = (ks * 8 + tg) * ASTR + nt * 8 + g;
                    uint32_t vh[2];
                    vh[0] = __float_as_uint(Vs[vc]);
                    vh[1] = __float_as_uint(Vs[vc + 4 * ASTR]);
                    mma_tf32(o[nt], ph, vh);
                }
            }
        }

        if (kb + 1 < nkb) CP_WAIT0();
        __syncthreads();
    }

    const int tailblk = nkb - (upper ? 1 : 0);
    const int cnt = SS - tailblk * 64;
    if (cnt > 0) {
        const float mn0 = fmaxf(m0, -8.0f), mn1 = fmaxf(m1, -8.0f);
        const float rs0 = __expf(m0 - mn0), rs1 = __expf(m1 - mn1);
        const float p0 = __expf(-8.0f - mn0), p1 = __expf(-8.0f - mn1);
        l0 = l0 * rs0 + (float)cnt * p0;
        l1 = l1 * rs1 + (float)cnt * p1;
        const float* vb = g_Vbs + ((size_t)bh * (NQB + 1) + tailblk) * DEP;
#pragma unroll
        for (int nt = 0; nt < 8; ++nt) {
            const int c = nt * 8 + 2 * tg;
            float2 vv = *(const float2*)(vb + c);
            o[nt][0] = o[nt][0] * rs0 + p0 * vv.x;
            o[nt][1] = o[nt][1] * rs0 + p0 * vv.y;
            o[nt][2] = o[nt][2] * rs1 + p1 * vv.x;
            o[nt][3] = o[nt][3] * rs1 + p1 * vv.y;
        }
    }

    const float inv0 = 1.f / l0, inv1 = 1.f / l1;
    const int b = bh >> 4, h = bh & 15;
    float* op0 = out + ((size_t)b * SS + q0 + row0) * DD + h * DEP;
    float* op1 = op0 + (size_t)8 * DD;
#pragma unroll
    for (int nt = 0; nt < 8; ++nt) {
        const int c = nt * 8 + 2 * tg;
        *(float2*)(op0 + c) = make_float2(o[nt][0] * inv0, o[nt][1] * inv0);
        *(float2*)(op1 + c) = make_float2(o[nt][2] * inv1, o[nt][3] * inv1);
    }
}

// ---------------------------------------------------------------------------
extern "C" void kernel_launch(void* const* d_in, const int* in_sizes, int n_in,
                              void* d_out, int out_size) {
    const float* q  = (const float*)d_in[0];
    const float* k  = (const float*)d_in[1];
    const float* v  = (const float*)d_in[2];
    // d_in[3] is the causal mask (tril) — handled analytically.
    const float* wq = (const float*)d_in[4];
    const float* wk = (const float*)d_in[5];
    const float* wv = (const float*)d_in[6];
    float* out = (float*)d_out;

    cudaFuncSetAttribute(proj_mma_kernel, cudaFuncAttributeMaxDynamicSharedMemorySize,
                         PROJ_SMEM);
    cudaFuncSetAttribute(attn_mma_kernel, cudaFuncAttributeMaxDynamicSharedMemorySize,
                         ATTN_SMEM);

    proj_mma_kernel<<<dim3(8, 32, 3), 256, PROJ_SMEM>>>(q, k, v, wq, wk, wv);
    vsuffix_part<<<dim3(NQB, BH), DEP>>>();
    vsuffix_scan<<<BH, DEP>>>();
    attn_mma_kernel<<<dim3(NQT, BH), 256, ATTN_SMEM>>>(out);
}